// round 5
// baseline (speedup 1.0000x reference)
#include <cuda_runtime.h>
#include <cuda_bf16.h>
#include <cstdint>

#define Bb 8
#define Nn 4096
#define ATTR 16
#define Hh 64
#define STEPS 8
#define CAP 128
#define ROWS (Bb*Nn)            // 32768

typedef unsigned long long ull;

// ------------------------- device scratch -------------------------
__device__ float g_h[ROWS*Hh];       // 8 MB
__device__ float g_ain[ROWS*Hh];     // 8 MB
__device__ float g_aout[ROWS*Hh];    // 8 MB
__device__ int   g_incnt[ROWS];
__device__ int   g_outcnt[ROWS];
__device__ int   g_incol[(size_t)ROWS*CAP];   // 16.8 MB
__device__ int   g_outcol[(size_t)ROWS*CAP];  // 16.8 MB
__device__ int   g_sink;

// ------------------------- helpers -------------------------
__device__ __forceinline__ float sigmoidf_(float x) { return 1.f / (1.f + __expf(-x)); }
__device__ __forceinline__ float tanhf_(float x) {
    float e = __expf(2.f * x); return 1.f - 2.f / (e + 1.f);
}
__device__ __forceinline__ uint32_t tf32hi(float x) {
    uint32_t u; asm("cvt.rna.tf32.f32 %0, %1;" : "=r"(u) : "f"(x));
    return u;
}
// hi = tf32(x); lo = x - hi (HW truncates extra mantissa bits of lo)
__device__ __forceinline__ void split2(float x, uint32_t &hi, uint32_t &lo) {
    hi = tf32hi(x);
    lo = __float_as_uint(x - __uint_as_float(hi));
}
__device__ __forceinline__ void mma8(float* d, uint32_t a0, uint32_t a1, uint32_t a2, uint32_t a3,
                                     uint32_t b0, uint32_t b1) {
    asm volatile(
        "mma.sync.aligned.m16n8k8.row.col.f32.tf32.tf32.f32 "
        "{%0,%1,%2,%3}, {%4,%5,%6,%7}, {%8,%9}, {%0,%1,%2,%3};"
        : "+f"(d[0]), "+f"(d[1]), "+f"(d[2]), "+f"(d[3])
        : "r"(a0), "r"(a1), "r"(a2), "r"(a3), "r"(b0), "r"(b1));
}
__device__ __forceinline__ void add2(ull &acc, ull v) {
    asm("add.rn.f32x2 %0, %0, %1;" : "+l"(acc) : "l"(v));
}

// ------------------------- small kernels -------------------------
__global__ void zero_counts() {
    int i = blockIdx.x * blockDim.x + threadIdx.x;
    if (i < ROWS) { g_incnt[i] = 0; g_outcnt[i] = 0; }
}

__global__ void probe() { if (threadIdx.x == 0) g_sink = g_incnt[0] & 0; }

__global__ void build_csr(const float* __restrict__ adj) {
    int row = blockIdx.x;
    int b   = row >> 12;
    int i   = row & (Nn - 1);
    const float4* a4 = reinterpret_cast<const float4*>(adj + (size_t)row * Nn);
    for (int t = threadIdx.x; t < Nn / 4; t += blockDim.x) {
        float4 v = a4[t];
        int j = 4 * t;
        #pragma unroll
        for (int u = 0; u < 4; u++) {
            float val = (u == 0) ? v.x : (u == 1) ? v.y : (u == 2) ? v.z : v.w;
            if (val != 0.f) {
                int jc = j + u;
                int p = atomicAdd(&g_incnt[row], 1);
                if (p < CAP) g_incol[(size_t)row * CAP + p] = jc;
                int q = atomicAdd(&g_outcnt[(b << 12) + jc], 1);
                if (q < CAP) g_outcol[((size_t)((b << 12) + jc)) * CAP + q] = i;
            }
        }
    }
}

__global__ void init_h(const float* __restrict__ attr,
                       const float* __restrict__ Wi,
                       const float* __restrict__ bi) {
    __shared__ float sWiT[ATTR * Hh];
    __shared__ float sAttr[4][ATTR];
    int col = threadIdx.x & 63;
    int r   = threadIdx.x >> 6;
    int row = blockIdx.x * 4 + r;
    for (int t = threadIdx.x; t < ATTR * Hh; t += 256) {
        int a = t >> 6, c = t & 63;
        sWiT[t] = Wi[c * ATTR + a];
    }
    if (col < ATTR) sAttr[r][col] = attr[(size_t)row * ATTR + col];
    __syncthreads();
    float acc = bi[col];
    #pragma unroll
    for (int a = 0; a < ATTR; a++) acc = fmaf(sAttr[r][a], sWiT[a * 64 + col], acc);
    g_h[(size_t)row * Hh + col] = fmaxf(acc, 0.f);
}

// ------------------------- spmm (unchanged from R2) -------------------------
__global__ void __launch_bounds__(256) spmm2() {
    int w    = threadIdx.x >> 5;
    int lane = threadIdx.x & 31;
    int row  = blockIdx.x * 4 + (w >> 1);
    int dir  = w & 1;
    int b    = row >> 12;
    const ull* __restrict__ hb = reinterpret_cast<const ull*>(g_h + ((size_t)(b << 12)) * Hh);
    const int* __restrict__ cl = (dir ? g_outcol : g_incol) + (size_t)row * CAP;
    int cnt = dir ? g_outcnt[row] : g_incnt[row];
    cnt = min(cnt, CAP);
    ull acc = 0;
    int t = 0;
    for (; t + 8 <= cnt; t += 8) {
        int j[8];
        #pragma unroll
        for (int u = 0; u < 8; u++) j[u] = __ldg(cl + t + u);
        ull v[8];
        #pragma unroll
        for (int u = 0; u < 8; u++) v[u] = hb[(size_t)j[u] * 32 + lane];
        #pragma unroll
        for (int u = 0; u < 8; u++) add2(acc, v[u]);
    }
    for (; t < cnt; t++) add2(acc, hb[(size_t)cl[t] * 32 + lane]);
    float* dst = (dir ? g_aout : g_ain) + (size_t)row * Hh;
    *reinterpret_cast<ull*>(dst + 2 * lane) = acc;
}

// ------------------------- GRU via mma.sync tf32 (3xTF32) -------------------------
// Per CTA tile: 64 rows x 192 outs. Persistent grid (148), W resident in smem.
// smem floats: sW[192][196] | sWh2[64][68] | sX[64][196] | bias[192]
#define WP   196
#define W2P  68
#define OFF_W    0
#define OFF_WH2  (192*WP)                 // 37632
#define OFF_X    (OFF_WH2 + 64*W2P)       // 41984
#define OFF_B    (OFF_X + 64*WP)          // 54528
#define GRUM_FLOATS (OFF_B + 192)         // 54720
#define GRUM_SMEM (GRUM_FLOATS*4)         // 218880
#define NTILE (ROWS/64)                   // 512

__global__ void __launch_bounds__(256, 1)
gru_m(const float* __restrict__ Wz, const float* __restrict__ bz,
      const float* __restrict__ Wr, const float* __restrict__ br,
      const float* __restrict__ Wh, const float* __restrict__ bh) {
    extern __shared__ float sm[];
    float* sW   = sm + OFF_W;
    float* sWh2 = sm + OFF_WH2;
    float* sX   = sm + OFF_X;
    float* sB   = sm + OFF_B;

    int tid  = threadIdx.x;
    int w    = tid >> 5;
    int lane = tid & 31;
    int g    = lane >> 2;     // 0..7
    int t    = lane & 3;      // 0..3
    int half = w & 1;
    int r0   = (w >> 1) * 16;

    // ---- stage weights once ----
    for (int idx = tid; idx < 192 * 48; idx += 256) {
        int n = idx / 48, q = idx - n * 48;
        int k = q * 4;
        float4 v;
        if (n < 64)            v = *reinterpret_cast<const float4*>(Wz + n * 192 + k);
        else if (n < 128)      v = *reinterpret_cast<const float4*>(Wr + (n - 64) * 192 + k);
        else if (k < 128)      v = *reinterpret_cast<const float4*>(Wh + (n - 128) * 192 + k);
        else                   v = make_float4(0.f, 0.f, 0.f, 0.f);
        *reinterpret_cast<float4*>(sW + n * WP + k) = v;
    }
    for (int idx = tid; idx < 64 * 16; idx += 256) {
        int n = idx >> 4, q = idx & 15;
        *reinterpret_cast<float4*>(sWh2 + n * W2P + q * 4) =
            *reinterpret_cast<const float4*>(Wh + n * 192 + 128 + q * 4);
    }
    for (int i = tid; i < 192; i += 256)
        sB[i] = (i < 64) ? bz[i] : (i < 128) ? br[i - 64] : bh[i - 128];

    // n-tile bases for this warp (phase A)
    int nb[12];
    #pragma unroll
    for (int j = 0; j < 8; j++)  nb[j] = half * 64 + j * 8;
    #pragma unroll
    for (int j = 8; j < 12; j++) nb[j] = 128 + half * 32 + (j - 8) * 8;

    __syncthreads();

    for (int tile = blockIdx.x; tile < NTILE; tile += gridDim.x) {
        int tb = tile * 64;
        // ---- stage X tile: [64 rows][a_in|a_out|h] ----
        for (int idx = tid; idx < 64 * 48; idx += 256) {
            int row = idx / 48, q = idx - row * 48;
            int c = q * 4;
            const float* src = (c < 64) ? (g_ain + (size_t)(tb + row) * 64 + c)
                             : (c < 128) ? (g_aout + (size_t)(tb + row) * 64 + c - 64)
                                         : (g_h + (size_t)(tb + row) * 64 + c - 128);
            *reinterpret_cast<float4*>(sX + row * WP + c) =
                *reinterpret_cast<const float4*>(src);
        }
        __syncthreads();

        float acc[12][4];
        #pragma unroll
        for (int j = 0; j < 12; j++) {
            acc[j][0] = 0.f; acc[j][1] = 0.f; acc[j][2] = 0.f; acc[j][3] = 0.f;
        }

        // ---- phase A: k = 0..191 ----
        const float* xbase = sX + (r0 + g) * WP + t;
        #pragma unroll 2
        for (int ks = 0; ks < 24; ks++) {
            int k0 = ks * 8;
            uint32_t aH[4], aL[4];
            split2(xbase[k0],            aH[0], aL[0]);
            split2(xbase[8 * WP + k0],   aH[1], aL[1]);
            split2(xbase[k0 + 4],        aH[2], aL[2]);
            split2(xbase[8 * WP + k0+4], aH[3], aL[3]);
            #pragma unroll
            for (int j = 0; j < 12; j++) {
                const float* wp = sW + (nb[j] + g) * WP + k0 + t;
                uint32_t bh0, bl0, bh1, bl1;
                split2(wp[0], bh0, bl0);
                split2(wp[4], bh1, bl1);
                mma8(acc[j], aH[0], aH[1], aH[2], aH[3], bh0, bh1);
                mma8(acc[j], aL[0], aL[1], aL[2], aL[3], bh0, bh1);
                mma8(acc[j], aH[0], aH[1], aH[2], aH[3], bl0, bl1);
            }
        }
        __syncthreads();

        // ---- epilogue 1: z -> sX[.,64..127], rh -> sX[.,0..63] ----
        {
            int ra = r0 + g, rb = r0 + g + 8;
            if (half) {
                #pragma unroll
                for (int j = 0; j < 8; j++) {
                    int c0 = j * 8 + 2 * t;
                    float b0 = sB[64 + c0], b1 = sB[64 + c0 + 1];
                    sX[ra * WP + c0]     = sigmoidf_(acc[j][0] + b0) * sX[ra * WP + 128 + c0];
                    sX[ra * WP + c0 + 1] = sigmoidf_(acc[j][1] + b1) * sX[ra * WP + 128 + c0 + 1];
                    sX[rb * WP + c0]     = sigmoidf_(acc[j][2] + b0) * sX[rb * WP + 128 + c0];
                    sX[rb * WP + c0 + 1] = sigmoidf_(acc[j][3] + b1) * sX[rb * WP + 128 + c0 + 1];
                }
            } else {
                #pragma unroll
                for (int j = 0; j < 8; j++) {
                    int c0 = j * 8 + 2 * t;
                    float b0 = sB[c0], b1 = sB[c0 + 1];
                    sX[ra * WP + 64 + c0]     = sigmoidf_(acc[j][0] + b0);
                    sX[ra * WP + 64 + c0 + 1] = sigmoidf_(acc[j][1] + b1);
                    sX[rb * WP + 64 + c0]     = sigmoidf_(acc[j][2] + b0);
                    sX[rb * WP + 64 + c0 + 1] = sigmoidf_(acc[j][3] + b1);
                }
            }
        }
        __syncthreads();

        // ---- phase B: hn += rh @ Wh2^T, k = 0..63 ----
        #pragma unroll
        for (int ks = 0; ks < 8; ks++) {
            int k0 = ks * 8;
            uint32_t aH[4], aL[4];
            split2(xbase[k0],            aH[0], aL[0]);
            split2(xbase[8 * WP + k0],   aH[1], aL[1]);
            split2(xbase[k0 + 4],        aH[2], aL[2]);
            split2(xbase[8 * WP + k0+4], aH[3], aL[3]);
            #pragma unroll
            for (int j = 0; j < 4; j++) {
                int n2 = half * 32 + j * 8;
                const float* wp = sWh2 + (n2 + g) * W2P + k0 + t;
                uint32_t bh0, bl0, bh1, bl1;
                split2(wp[0], bh0, bl0);
                split2(wp[4], bh1, bl1);
                mma8(acc[8 + j], aH[0], aH[1], aH[2], aH[3], bh0, bh1);
                mma8(acc[8 + j], aL[0], aL[1], aL[2], aL[3], bh0, bh1);
                mma8(acc[8 + j], aH[0], aH[1], aH[2], aH[3], bl0, bl1);
            }
        }
        __syncthreads();

        // ---- hn -> sX[.,0..63] ----
        {
            int ra = r0 + g, rb = r0 + g + 8;
            #pragma unroll
            for (int j = 0; j < 4; j++) {
                int c0 = half * 32 + j * 8 + 2 * t;
                float b0 = sB[128 + c0], b1 = sB[128 + c0 + 1];
                sX[ra * WP + c0]     = tanhf_(acc[8 + j][0] + b0);
                sX[ra * WP + c0 + 1] = tanhf_(acc[8 + j][1] + b1);
                sX[rb * WP + c0]     = tanhf_(acc[8 + j][2] + b0);
                sX[rb * WP + c0 + 1] = tanhf_(acc[8 + j][3] + b1);
            }
        }
        __syncthreads();

        // ---- final update: h' = h + z*(hn - h) ----
        {
            int row = tid >> 2;
            int cb  = (tid & 3) * 16;
            #pragma unroll
            for (int u = 0; u < 4; u++) {
                int cc = cb + u * 4;
                float4 hn4 = *reinterpret_cast<float4*>(sX + row * WP + cc);
                float4 z4  = *reinterpret_cast<float4*>(sX + row * WP + 64 + cc);
                float4 h4  = *reinterpret_cast<float4*>(sX + row * WP + 128 + cc);
                float4 o;
                o.x = h4.x + z4.x * (hn4.x - h4.x);
                o.y = h4.y + z4.y * (hn4.y - h4.y);
                o.z = h4.z + z4.z * (hn4.z - h4.z);
                o.w = h4.w + z4.w * (hn4.w - h4.w);
                *reinterpret_cast<float4*>(g_h + (size_t)(tb + row) * 64 + cc) = o;
            }
        }
        __syncthreads();   // sX reuse next tile
    }
}

// out[row] = dot(h[row], Wo) + bo
__global__ void out_k(const float* __restrict__ Wo, const float* __restrict__ bo,
                      float* __restrict__ out) {
    int row  = blockIdx.x * 8 + (threadIdx.x >> 5);
    int lane = threadIdx.x & 31;
    const float* hr = g_h + (size_t)row * Hh;
    float a = hr[lane] * Wo[lane] + hr[lane + 32] * Wo[lane + 32];
    #pragma unroll
    for (int o = 16; o; o >>= 1) a += __shfl_xor_sync(0xffffffffu, a, o);
    if (lane == 0) out[row] = a + bo[0];
}

// ------------------------- launch -------------------------
extern "C" void kernel_launch(void* const* d_in, const int* in_sizes, int n_in,
                              void* d_out, int out_size) {
    const float* attr = (const float*)d_in[0];
    const float* adj  = (const float*)d_in[1];
    const float* Wi   = (const float*)d_in[2];
    const float* bi   = (const float*)d_in[3];
    const float* Wz   = (const float*)d_in[4];
    const float* bz   = (const float*)d_in[5];
    const float* Wr   = (const float*)d_in[6];
    const float* br   = (const float*)d_in[7];
    const float* Wh   = (const float*)d_in[8];
    const float* bh   = (const float*)d_in[9];
    const float* Wo   = (const float*)d_in[10];
    const float* bo   = (const float*)d_in[11];
    float* out = (float*)d_out;

    static bool attr_set = false;
    if (!attr_set) {
        cudaFuncSetAttribute(gru_m, cudaFuncAttributeMaxDynamicSharedMemorySize, GRUM_SMEM);
        attr_set = true;
    }

    zero_counts<<<(ROWS + 255) / 256, 256>>>();
    build_csr<<<ROWS, 256>>>(adj);
    init_h<<<ROWS / 4, 256>>>(attr, Wi, bi);
    probe<<<1, 32>>>();   // aligns ncu -s 5 onto gru_m
    for (int s = 0; s < STEPS; s++) {
        spmm2<<<ROWS / 4, 256>>>();
        gru_m<<<148, 256, GRUM_SMEM>>>(Wz, bz, Wr, br, Wh, bh);
    }
    out_k<<<ROWS / 8, 256>>>(Wo, bo, out);
}